// round 13
// baseline (speedup 1.0000x reference)
#include <cuda_runtime.h>
#include <cuda_fp16.h>
#include <cstdint>

// SparseLinearV: y = scatter(W_coo) @ x + bias
// Round 13: resubmit of R12 (never ran — GPU acquisition timeout, infra).
// R11 (500.7us) confirmed fp16 m16n8k16 is double-rate; GEMM is on the
// legacy HMMA pipe ceiling (~620 MACs/SM/cyc). Remaining fat is the
// preprocessing tail (~85us). This round: scatter COO directly into the fp16
// k-permuted weight buffer with native half atomics (perm applied in the
// scatter address), deleting the fp32 staging buffer, its zero pass, and the
// 96MB convert pass. GEMM kernel unchanged (protect the measured win).

#define IN_F   4096
#define OUT_F  4096
#define NCOLS  4096

__device__ __half g_Wh [(size_t)IN_F * OUT_F];   // W (M x K), k-permuted fp16
__device__ __half g_XTh[(size_t)NCOLS * OUT_F];  // x^T (N x K), k-permuted fp16

// ---------------------------------------------------------------------------
// helpers
// ---------------------------------------------------------------------------
__device__ __forceinline__ void cp_async16(uint32_t smem_dst, const void* gsrc) {
    asm volatile("cp.async.cg.shared.global [%0], [%1], 16;" :: "r"(smem_dst), "l"(gsrc));
}
__device__ __forceinline__ void cp_commit() { asm volatile("cp.async.commit_group;"); }
template<int N> __device__ __forceinline__ void cp_wait() {
    asm volatile("cp.async.wait_group %0;" :: "n"(N) : "memory");
}
__device__ __forceinline__ uint32_t smem_u32(const void* p) {
    uint32_t a;
    asm("{ .reg .u64 t; cvta.to.shared.u64 t, %1; cvt.u32.u64 %0, t; }" : "=r"(a) : "l"(p));
    return a;
}
__device__ __forceinline__ void mma_f16(float c[4], const unsigned a[4], const unsigned b[2]) {
    asm volatile(
        "mma.sync.aligned.m16n8k16.row.col.f32.f16.f16.f32 "
        "{%0,%1,%2,%3}, {%4,%5,%6,%7}, {%8,%9}, {%0,%1,%2,%3};"
        : "+f"(c[0]), "+f"(c[1]), "+f"(c[2]), "+f"(c[3])
        : "r"(a[0]), "r"(a[1]), "r"(a[2]), "r"(a[3]), "r"(b[0]), "r"(b[1]));
}
__device__ __forceinline__ uint32_t h2u(__half2 h) {
    return *reinterpret_cast<uint32_t*>(&h);
}

// ---------------------------------------------------------------------------
// Preprocessing
// ---------------------------------------------------------------------------
__global__ void zero_Wh_kernel() {
    size_t n8 = (size_t)IN_F * OUT_F / 8;   // uint4 = 8 halves
    uint4 z = make_uint4(0u, 0u, 0u, 0u);
    uint4* p = reinterpret_cast<uint4*>(g_Wh);
    for (size_t i = (size_t)blockIdx.x * blockDim.x + threadIdx.x;
         i < n8; i += (size_t)gridDim.x * blockDim.x)
        p[i] = z;
}

// COO scatter straight into fp16, k-permutation applied in the address.
// Within each 16-group, src k index s maps to dst d:
//   s<8:  d = (s>>1)*4 + (s&1)
//   s>=8: d = ((s-8)>>1)*4 + 2 + (s&1)
// (inverse of the dst ordering 0,1,8,9, 2,3,10,11, 4,5,12,13, 6,7,14,15)
__global__ void scatter_half_kernel(const int* __restrict__ rows,
                                    const int* __restrict__ cols,
                                    const float* __restrict__ vals, int nnz) {
    int i = blockIdx.x * blockDim.x + threadIdx.x;
    if (i < nnz) {
        const int k = cols[i];
        const int s = k & 15;
        const int d = (s < 8) ? ((s >> 1) * 4 + (s & 1))
                              : (((s - 8) >> 1) * 4 + 2 + (s & 1));
        const size_t idx = (size_t)rows[i] * OUT_F + (k & ~15) + d;
        atomicAdd(&g_Wh[idx], __float2half(vals[i]));
    }
}

// x (K x N) fp32 row-major -> g_XTh (N x K) fp16 row-major, k-permuted.
__global__ void transpose_convert_perm_kernel(const float* __restrict__ x) {
    __shared__ float t[32][33];   // t[k_local][n_local]
    const int bx = blockIdx.x * 32;  // n base
    const int by = blockIdx.y * 32;  // k base
    const int tx = threadIdx.x, ty = threadIdx.y;
#pragma unroll
    for (int i = 0; i < 4; i++)
        t[ty + 8 * i][tx] = x[(size_t)(by + ty + 8 * i) * NCOLS + bx + tx];
    __syncthreads();
    // Each thread writes one permuted quad (4 halves = 8 B).
    const int qc = tx & 7;             // quad 0..7 within 32 k
    const int nl = (tx >> 3) * 8 + ty; // 0..31
    const int grp = qc >> 2;           // 16-group 0..1
    const int q4  = qc & 3;            // quad within group
    const int s0 = grp * 16 + 2 * q4;  // src k of first pair
    const int s2 = s0 + 8;             // src k of second pair
    uint2 out;
    out.x = h2u(__floats2half2_rn(t[s0][nl], t[s0 + 1][nl]));
    out.y = h2u(__floats2half2_rn(t[s2][nl], t[s2 + 1][nl]));
    *reinterpret_cast<uint2*>(&g_XTh[(size_t)(bx + nl) * OUT_F + by + grp * 16 + q4 * 4]) = out;
}

// ---------------------------------------------------------------------------
// GEMM: C(4096x4096) = W @ x + bias  (A = g_Wh, B = g_XTh, both K-major fp16)
//   BM=128, BN=128, BK=32, 256 threads, warp tile 64x32, double buffer.
//   smem row stride 48 halves (24 words): conflict-free LDS.64 phases.
//   (unchanged from R11 — measured 500.7us total)
// ---------------------------------------------------------------------------
#define BM 128
#define BN 128
#define BK 32
#define NT (OUT_F / BK)            // 128
#define AST 48                     // halves per smem row (32 data + 16 pad)
#define TILE_HALVES (BM * AST)     // 6144 halves = 12288 B
#define STAGE_HALVES (2 * TILE_HALVES)
#define SMEM_TOTAL (2 * STAGE_HALVES * 2)   // 49152 B

__global__ __launch_bounds__(256, 2)
void gemm_f16_kernel(const float* __restrict__ bias, float* __restrict__ C) {
    extern __shared__ __align__(16) __half smem[];
    __half* As[2] = { smem, smem + STAGE_HALVES };
    __half* Bs[2] = { smem + TILE_HALVES, smem + STAGE_HALVES + TILE_HALVES };

    const int tid  = threadIdx.x;
    const int lane = tid & 31;
    const int wid  = tid >> 5;
    const int wm   = wid & 1;         // 0..1  (M direction, 64 rows)
    const int wn   = wid >> 1;        // 0..3  (N direction, 32 cols)
    const int r    = lane >> 2;       // 0..7
    const int c    = lane & 3;        // 0..3
    const int c2   = c * 2;           // epilogue col pair

    const int rowBase = blockIdx.y * BM;
    const int colBase = blockIdx.x * BN;

    const uint32_t sA[2] = { smem_u32(As[0]), smem_u32(As[1]) };
    const uint32_t sB[2] = { smem_u32(Bs[0]), smem_u32(Bs[1]) };

    auto load_stage = [&](int s, int k0) {
#pragma unroll
        for (int l = 0; l < 2; l++) {
            const int ch  = tid + 256 * l;
            const int row = ch >> 2;
            const int c16 = ch & 3;
            cp_async16(sA[s] + (uint32_t)(row * AST + c16 * 8) * 2,
                       &g_Wh[(size_t)(rowBase + row) * OUT_F + k0 + c16 * 8]);
        }
#pragma unroll
        for (int l = 0; l < 2; l++) {
            const int ch  = tid + 256 * l;
            const int row = ch >> 2;
            const int c16 = ch & 3;
            cp_async16(sB[s] + (uint32_t)(row * AST + c16 * 8) * 2,
                       &g_XTh[(size_t)(colBase + row) * OUT_F + k0 + c16 * 8]);
        }
        cp_commit();
    };

    float acc[4][4][4];
#pragma unroll
    for (int i = 0; i < 4; i++)
#pragma unroll
        for (int j = 0; j < 4; j++)
#pragma unroll
            for (int q = 0; q < 4; q++) acc[i][j][q] = 0.f;

    load_stage(0, 0);

    for (int t = 0; t < NT; t++) {
        const int cur = t & 1;
        if (t + 1 < NT) load_stage(cur ^ 1, (t + 1) * BK);
        cp_wait<1>();
        __syncthreads();

        const __half* Ab = As[cur];
        const __half* Bb = Bs[cur];
#pragma unroll
        for (int ks = 0; ks < 2; ks++) {
            const int kh = ks * 16 + c * 4;
            unsigned afr[4][4], bfr[4][2];
#pragma unroll
            for (int i = 0; i < 4; i++) {
                const int m = wm * 64 + i * 16 + r;
                uint2 p0 = *reinterpret_cast<const uint2*>(&Ab[m * AST + kh]);
                uint2 p1 = *reinterpret_cast<const uint2*>(&Ab[(m + 8) * AST + kh]);
                afr[i][0] = p0.x;
                afr[i][1] = p1.x;
                afr[i][2] = p0.y;
                afr[i][3] = p1.y;
            }
#pragma unroll
            for (int j = 0; j < 4; j++) {
                const int n = wn * 32 + j * 8 + r;
                uint2 q = *reinterpret_cast<const uint2*>(&Bb[n * AST + kh]);
                bfr[j][0] = q.x;
                bfr[j][1] = q.y;
            }
#pragma unroll
            for (int i = 0; i < 4; i++)
#pragma unroll
                for (int j = 0; j < 4; j++)
                    mma_f16(acc[i][j], afr[i], bfr[j]);
        }
        __syncthreads();
    }

    // Epilogue: bias add + float2 stores.
#pragma unroll
    for (int i = 0; i < 4; i++) {
        const int row0 = rowBase + wm * 64 + i * 16 + r;
#pragma unroll
        for (int j = 0; j < 4; j++) {
            const int col = colBase + wn * 32 + j * 8 + c2;
            float2 bv = *reinterpret_cast<const float2*>(&bias[col]);
            float2 o0 = make_float2(acc[i][j][0] + bv.x, acc[i][j][1] + bv.y);
            float2 o1 = make_float2(acc[i][j][2] + bv.x, acc[i][j][3] + bv.y);
            *reinterpret_cast<float2*>(&C[(size_t)row0 * NCOLS + col])       = o0;
            *reinterpret_cast<float2*>(&C[(size_t)(row0 + 8) * NCOLS + col]) = o1;
        }
    }
}

// ---------------------------------------------------------------------------
// Launch
// ---------------------------------------------------------------------------
extern "C" void kernel_launch(void* const* d_in, const int* in_sizes, int n_in,
                              void* d_out, int out_size) {
    const float* x    = (const float*)d_in[0];
    const int*   rows = (const int*)d_in[1];
    const int*   cols = (const int*)d_in[2];
    const float* vals = (const float*)d_in[3];
    const float* bias = (const float*)d_in[4];
    float*       y    = (float*)d_out;
    const int nnz = in_sizes[1];

    cudaFuncSetAttribute(gemm_f16_kernel,
                         cudaFuncAttributeMaxDynamicSharedMemorySize, SMEM_TOTAL);

    zero_Wh_kernel<<<1184, 256>>>();
    scatter_half_kernel<<<(nnz + 255) / 256, 256>>>(rows, cols, vals, nnz);
    transpose_convert_perm_kernel<<<dim3(NCOLS / 32, OUT_F / 32), dim3(32, 8)>>>(x);

    dim3 grid(NCOLS / BN, IN_F / BM);  // 32 x 32 = 1024 CTAs
    gemm_f16_kernel<<<grid, 256, SMEM_TOTAL>>>(bias, y);
}

// round 14
// speedup vs baseline: 1.0827x; 1.0827x over previous
#include <cuda_runtime.h>
#include <cuda_fp16.h>
#include <cstdint>

// SparseLinearV: y = scatter(W_coo) @ x + bias
// Round 14: R13 profile showed GEMM tensor pipe only 51.6% busy (NOT
// saturated — R8's conclusion revised). The leak is barrier/drain exposure:
// 256 __syncthreads per CTA (2 per ktile) + prefetch depth 1. This round:
// 3-stage cp.async pipeline with ONE barrier per iteration (load t+2 into
// stage (t+2)%3 after the barrier; overwriting stage (t-1)%3 is safe since
// all warps passed the barrier after computing it). Fragment code, AST=48
// conflict-free layout, warp mapping, preprocessing all unchanged from R13.

#define IN_F   4096
#define OUT_F  4096
#define NCOLS  4096

__device__ __half g_Wh [(size_t)IN_F * OUT_F];   // W (M x K), k-permuted fp16
__device__ __half g_XTh[(size_t)NCOLS * OUT_F];  // x^T (N x K), k-permuted fp16

// ---------------------------------------------------------------------------
// helpers
// ---------------------------------------------------------------------------
__device__ __forceinline__ void cp_async16(uint32_t smem_dst, const void* gsrc) {
    asm volatile("cp.async.cg.shared.global [%0], [%1], 16;" :: "r"(smem_dst), "l"(gsrc));
}
__device__ __forceinline__ void cp_commit() { asm volatile("cp.async.commit_group;"); }
template<int N> __device__ __forceinline__ void cp_wait() {
    asm volatile("cp.async.wait_group %0;" :: "n"(N) : "memory");
}
__device__ __forceinline__ uint32_t smem_u32(const void* p) {
    uint32_t a;
    asm("{ .reg .u64 t; cvta.to.shared.u64 t, %1; cvt.u32.u64 %0, t; }" : "=r"(a) : "l"(p));
    return a;
}
__device__ __forceinline__ void mma_f16(float c[4], const unsigned a[4], const unsigned b[2]) {
    asm volatile(
        "mma.sync.aligned.m16n8k16.row.col.f32.f16.f16.f32 "
        "{%0,%1,%2,%3}, {%4,%5,%6,%7}, {%8,%9}, {%0,%1,%2,%3};"
        : "+f"(c[0]), "+f"(c[1]), "+f"(c[2]), "+f"(c[3])
        : "r"(a[0]), "r"(a[1]), "r"(a[2]), "r"(a[3]), "r"(b[0]), "r"(b[1]));
}
__device__ __forceinline__ uint32_t h2u(__half2 h) {
    return *reinterpret_cast<uint32_t*>(&h);
}

// ---------------------------------------------------------------------------
// Preprocessing (unchanged from R13)
// ---------------------------------------------------------------------------
__global__ void zero_Wh_kernel() {
    size_t n8 = (size_t)IN_F * OUT_F / 8;   // uint4 = 8 halves
    uint4 z = make_uint4(0u, 0u, 0u, 0u);
    uint4* p = reinterpret_cast<uint4*>(g_Wh);
    for (size_t i = (size_t)blockIdx.x * blockDim.x + threadIdx.x;
         i < n8; i += (size_t)gridDim.x * blockDim.x)
        p[i] = z;
}

// COO scatter straight into fp16, k-permutation applied in the address.
__global__ void scatter_half_kernel(const int* __restrict__ rows,
                                    const int* __restrict__ cols,
                                    const float* __restrict__ vals, int nnz) {
    int i = blockIdx.x * blockDim.x + threadIdx.x;
    if (i < nnz) {
        const int k = cols[i];
        const int s = k & 15;
        const int d = (s < 8) ? ((s >> 1) * 4 + (s & 1))
                              : (((s - 8) >> 1) * 4 + 2 + (s & 1));
        const size_t idx = (size_t)rows[i] * OUT_F + (k & ~15) + d;
        atomicAdd(&g_Wh[idx], __float2half(vals[i]));
    }
}

// x (K x N) fp32 row-major -> g_XTh (N x K) fp16 row-major, k-permuted.
__global__ void transpose_convert_perm_kernel(const float* __restrict__ x) {
    __shared__ float t[32][33];   // t[k_local][n_local]
    const int bx = blockIdx.x * 32;  // n base
    const int by = blockIdx.y * 32;  // k base
    const int tx = threadIdx.x, ty = threadIdx.y;
#pragma unroll
    for (int i = 0; i < 4; i++)
        t[ty + 8 * i][tx] = x[(size_t)(by + ty + 8 * i) * NCOLS + bx + tx];
    __syncthreads();
    const int qc = tx & 7;             // quad 0..7 within 32 k
    const int nl = (tx >> 3) * 8 + ty; // 0..31
    const int grp = qc >> 2;           // 16-group 0..1
    const int q4  = qc & 3;            // quad within group
    const int s0 = grp * 16 + 2 * q4;
    const int s2 = s0 + 8;
    uint2 out;
    out.x = h2u(__floats2half2_rn(t[s0][nl], t[s0 + 1][nl]));
    out.y = h2u(__floats2half2_rn(t[s2][nl], t[s2 + 1][nl]));
    *reinterpret_cast<uint2*>(&g_XTh[(size_t)(bx + nl) * OUT_F + by + grp * 16 + q4 * 4]) = out;
}

// ---------------------------------------------------------------------------
// GEMM: C(4096x4096) = W @ x + bias  (A = g_Wh, B = g_XTh, both K-major fp16)
//   BM=128, BN=128, BK=32, 256 threads, warp tile 64x32.
//   3-stage cp.async pipeline, ONE __syncthreads per ktile.
// ---------------------------------------------------------------------------
#define BM 128
#define BN 128
#define BK 32
#define NT (OUT_F / BK)            // 128
#define NSTAGE 3
#define AST 48                     // halves per smem row (32 data + 16 pad)
#define TILE_HALVES (BM * AST)     // 6144 halves = 12288 B
#define STAGE_HALVES (2 * TILE_HALVES)          // A tile + B tile
#define SMEM_TOTAL (NSTAGE * STAGE_HALVES * 2)  // 73728 B

__global__ __launch_bounds__(256, 2)
void gemm_f16_kernel(const float* __restrict__ bias, float* __restrict__ C) {
    extern __shared__ __align__(16) __half smem[];

    const int tid  = threadIdx.x;
    const int lane = tid & 31;
    const int wid  = tid >> 5;
    const int wm   = wid & 1;         // 0..1  (M direction, 64 rows)
    const int wn   = wid >> 1;        // 0..3  (N direction, 32 cols)
    const int r    = lane >> 2;       // 0..7
    const int c    = lane & 3;        // 0..3
    const int c2   = c * 2;           // epilogue col pair

    const int rowBase = blockIdx.y * BM;
    const int colBase = blockIdx.x * BN;

    uint32_t sA[NSTAGE], sB[NSTAGE];
#pragma unroll
    for (int s = 0; s < NSTAGE; s++) {
        sA[s] = smem_u32(smem + s * STAGE_HALVES);
        sB[s] = sA[s] + TILE_HALVES * 2;   // bytes
    }

    // Loader: 16B chunk = 8 halves. A tile: 128 rows x 4 chunks = 512 chunks,
    // 2 per thread; B likewise. (Issues one commit_group.)
    auto load_stage = [&](int s, int k0) {
#pragma unroll
        for (int l = 0; l < 2; l++) {
            const int ch  = tid + 256 * l;
            const int row = ch >> 2;
            const int c16 = ch & 3;
            cp_async16(sA[s] + (uint32_t)(row * AST + c16 * 8) * 2,
                       &g_Wh[(size_t)(rowBase + row) * OUT_F + k0 + c16 * 8]);
        }
#pragma unroll
        for (int l = 0; l < 2; l++) {
            const int ch  = tid + 256 * l;
            const int row = ch >> 2;
            const int c16 = ch & 3;
            cp_async16(sB[s] + (uint32_t)(row * AST + c16 * 8) * 2,
                       &g_XTh[(size_t)(colBase + row) * OUT_F + k0 + c16 * 8]);
        }
        cp_commit();
    };

    float acc[4][4][4];
#pragma unroll
    for (int i = 0; i < 4; i++)
#pragma unroll
        for (int j = 0; j < 4; j++)
#pragma unroll
            for (int q = 0; q < 4; q++) acc[i][j][q] = 0.f;

    // Prologue: prefetch tiles 0 and 1 (two commit groups in flight).
    load_stage(0, 0);
    load_stage(1, BK);

    int cur = 0;                       // stage of tile t
    int nxt2 = 2;                      // stage of tile t+2

    for (int t = 0; t < NT; t++) {
        cp_wait<1>();                  // group t complete (t+1 may be in flight)
        __syncthreads();               // all warps done with stage (t-1)%3

        // Prefetch tile t+2 into stage (t+2)%3 == (t-1)%3 — safe after barrier.
        if (t + 2 < NT) {
            load_stage(nxt2, (t + 2) * BK);
        } else {
            cp_commit();               // empty group keeps wait<1> accounting exact
        }

        const __half* Ab = reinterpret_cast<const __half*>(smem) + cur * STAGE_HALVES;
        const __half* Bb = Ab + TILE_HALVES;
#pragma unroll
        for (int ks = 0; ks < 2; ks++) {
            const int kh = ks * 16 + c * 4;
            unsigned afr[4][4], bfr[4][2];
#pragma unroll
            for (int i = 0; i < 4; i++) {
                const int m = wm * 64 + i * 16 + r;
                uint2 p0 = *reinterpret_cast<const uint2*>(&Ab[m * AST + kh]);
                uint2 p1 = *reinterpret_cast<const uint2*>(&Ab[(m + 8) * AST + kh]);
                afr[i][0] = p0.x;
                afr[i][1] = p1.x;
                afr[i][2] = p0.y;
                afr[i][3] = p1.y;
            }
#pragma unroll
            for (int j = 0; j < 4; j++) {
                const int n = wn * 32 + j * 8 + r;
                uint2 q = *reinterpret_cast<const uint2*>(&Bb[n * AST + kh]);
                bfr[j][0] = q.x;
                bfr[j][1] = q.y;
            }
#pragma unroll
            for (int i = 0; i < 4; i++)
#pragma unroll
                for (int j = 0; j < 4; j++)
                    mma_f16(acc[i][j], afr[i], bfr[j]);
        }

        cur  = (cur == NSTAGE - 1) ? 0 : cur + 1;
        nxt2 = (nxt2 == NSTAGE - 1) ? 0 : nxt2 + 1;
    }

    // Epilogue: bias add + float2 stores (bias hoisted per j).
    float2 bv[4];
#pragma unroll
    for (int j = 0; j < 4; j++)
        bv[j] = *reinterpret_cast<const float2*>(&bias[colBase + wn * 32 + j * 8 + c2]);
#pragma unroll
    for (int i = 0; i < 4; i++) {
        const int row0 = rowBase + wm * 64 + i * 16 + r;
#pragma unroll
        for (int j = 0; j < 4; j++) {
            const int col = colBase + wn * 32 + j * 8 + c2;
            float2 o0 = make_float2(acc[i][j][0] + bv[j].x, acc[i][j][1] + bv[j].y);
            float2 o1 = make_float2(acc[i][j][2] + bv[j].x, acc[i][j][3] + bv[j].y);
            *reinterpret_cast<float2*>(&C[(size_t)row0 * NCOLS + col])       = o0;
            *reinterpret_cast<float2*>(&C[(size_t)(row0 + 8) * NCOLS + col]) = o1;
        }
    }
}

// ---------------------------------------------------------------------------
// Launch
// ---------------------------------------------------------------------------
extern "C" void kernel_launch(void* const* d_in, const int* in_sizes, int n_in,
                              void* d_out, int out_size) {
    const float* x    = (const float*)d_in[0];
    const int*   rows = (const int*)d_in[1];
    const int*   cols = (const int*)d_in[2];
    const float* vals = (const float*)d_in[3];
    const float* bias = (const float*)d_in[4];
    float*       y    = (float*)d_out;
    const int nnz = in_sizes[1];

    cudaFuncSetAttribute(gemm_f16_kernel,
                         cudaFuncAttributeMaxDynamicSharedMemorySize, SMEM_TOTAL);

    zero_Wh_kernel<<<1184, 256>>>();
    scatter_half_kernel<<<(nnz + 255) / 256, 256>>>(rows, cols, vals, nnz);
    transpose_convert_perm_kernel<<<dim3(NCOLS / 32, OUT_F / 32), dim3(32, 8)>>>(x);

    dim3 grid(NCOLS / BN, IN_F / BM);  // 32 x 32 = 1024 CTAs
    gemm_f16_kernel<<<grid, 256, SMEM_TOTAL>>>(bias, y);
}

// round 16
// speedup vs baseline: 1.1559x; 1.0676x over previous
#include <cuda_runtime.h>
#include <cuda_fp16.h>
#include <cstdint>

// SparseLinearV: y = scatter(W_coo) @ x + bias
// Round 16: resubmit of R15 (never ran — GPU acquisition timeout, infra).
// R14 (463.1us, tensor 56.5%) showed a ~360-cyc fixed bubble per mainloop
// iteration (barrier + cp_wait + LDS refill). Amortize it: BK 32->64 halves
// the iteration count (128->64) and doubles per-iteration tensor work.
// 2-stage pipeline (41KB/stage, 82KB/CTA -> still 2 CTAs/SM), one barrier
// per iteration, cp_wait<0> (each load overlaps a full compute phase).
// AST=80 halves keeps the conflict-free LDS.64 property (r*40 mod 32 =
// {0,8,16,24}). Fragments/warp-map/preprocessing unchanged from R14.

#define IN_F   4096
#define OUT_F  4096
#define NCOLS  4096

__device__ __half g_Wh [(size_t)IN_F * OUT_F];   // W (M x K), k-permuted fp16
__device__ __half g_XTh[(size_t)NCOLS * OUT_F];  // x^T (N x K), k-permuted fp16

// ---------------------------------------------------------------------------
// helpers
// ---------------------------------------------------------------------------
__device__ __forceinline__ void cp_async16(uint32_t smem_dst, const void* gsrc) {
    asm volatile("cp.async.cg.shared.global [%0], [%1], 16;" :: "r"(smem_dst), "l"(gsrc));
}
__device__ __forceinline__ void cp_commit() { asm volatile("cp.async.commit_group;"); }
template<int N> __device__ __forceinline__ void cp_wait() {
    asm volatile("cp.async.wait_group %0;" :: "n"(N) : "memory");
}
__device__ __forceinline__ uint32_t smem_u32(const void* p) {
    uint32_t a;
    asm("{ .reg .u64 t; cvta.to.shared.u64 t, %1; cvt.u32.u64 %0, t; }" : "=r"(a) : "l"(p));
    return a;
}
__device__ __forceinline__ void mma_f16(float c[4], const unsigned a[4], const unsigned b[2]) {
    asm volatile(
        "mma.sync.aligned.m16n8k16.row.col.f32.f16.f16.f32 "
        "{%0,%1,%2,%3}, {%4,%5,%6,%7}, {%8,%9}, {%0,%1,%2,%3};"
        : "+f"(c[0]), "+f"(c[1]), "+f"(c[2]), "+f"(c[3])
        : "r"(a[0]), "r"(a[1]), "r"(a[2]), "r"(a[3]), "r"(b[0]), "r"(b[1]));
}
__device__ __forceinline__ uint32_t h2u(__half2 h) {
    return *reinterpret_cast<uint32_t*>(&h);
}

// ---------------------------------------------------------------------------
// Preprocessing (unchanged)
// ---------------------------------------------------------------------------
__global__ void zero_Wh_kernel() {
    size_t n8 = (size_t)IN_F * OUT_F / 8;
    uint4 z = make_uint4(0u, 0u, 0u, 0u);
    uint4* p = reinterpret_cast<uint4*>(g_Wh);
    for (size_t i = (size_t)blockIdx.x * blockDim.x + threadIdx.x;
         i < n8; i += (size_t)gridDim.x * blockDim.x)
        p[i] = z;
}

__global__ void scatter_half_kernel(const int* __restrict__ rows,
                                    const int* __restrict__ cols,
                                    const float* __restrict__ vals, int nnz) {
    int i = blockIdx.x * blockDim.x + threadIdx.x;
    if (i < nnz) {
        const int k = cols[i];
        const int s = k & 15;
        const int d = (s < 8) ? ((s >> 1) * 4 + (s & 1))
                              : (((s - 8) >> 1) * 4 + 2 + (s & 1));
        const size_t idx = (size_t)rows[i] * OUT_F + (k & ~15) + d;
        atomicAdd(&g_Wh[idx], __float2half(vals[i]));
    }
}

__global__ void transpose_convert_perm_kernel(const float* __restrict__ x) {
    __shared__ float t[32][33];
    const int bx = blockIdx.x * 32;  // n base
    const int by = blockIdx.y * 32;  // k base
    const int tx = threadIdx.x, ty = threadIdx.y;
#pragma unroll
    for (int i = 0; i < 4; i++)
        t[ty + 8 * i][tx] = x[(size_t)(by + ty + 8 * i) * NCOLS + bx + tx];
    __syncthreads();
    const int qc = tx & 7;
    const int nl = (tx >> 3) * 8 + ty;
    const int grp = qc >> 2;
    const int q4  = qc & 3;
    const int s0 = grp * 16 + 2 * q4;
    const int s2 = s0 + 8;
    uint2 out;
    out.x = h2u(__floats2half2_rn(t[s0][nl], t[s0 + 1][nl]));
    out.y = h2u(__floats2half2_rn(t[s2][nl], t[s2 + 1][nl]));
    *reinterpret_cast<uint2*>(&g_XTh[(size_t)(bx + nl) * OUT_F + by + grp * 16 + q4 * 4]) = out;
}

// ---------------------------------------------------------------------------
// GEMM: C(4096x4096) = W @ x + bias  (A = g_Wh, B = g_XTh, both K-major fp16)
//   BM=128, BN=128, BK=64, 256 threads, warp tile 64x32.
//   2-stage cp.async pipeline, ONE __syncthreads per ktile (64 iterations).
// ---------------------------------------------------------------------------
#define BM 128
#define BN 128
#define BK 64
#define NT (OUT_F / BK)            // 64
#define NSTAGE 2
#define AST 80                     // halves per smem row (64 data + 16 pad)
#define TILE_HALVES (BM * AST)     // 10240 halves = 20480 B
#define STAGE_HALVES (2 * TILE_HALVES)          // A tile + B tile = 40960 B
#define SMEM_TOTAL (NSTAGE * STAGE_HALVES * 2)  // 81920 B

__global__ __launch_bounds__(256, 2)
void gemm_f16_kernel(const float* __restrict__ bias, float* __restrict__ C) {
    extern __shared__ __align__(16) __half smem[];

    const int tid  = threadIdx.x;
    const int lane = tid & 31;
    const int wid  = tid >> 5;
    const int wm   = wid & 1;         // 0..1  (M direction, 64 rows)
    const int wn   = wid >> 1;        // 0..3  (N direction, 32 cols)
    const int r    = lane >> 2;       // 0..7
    const int c    = lane & 3;        // 0..3
    const int c2   = c * 2;           // epilogue col pair

    const int rowBase = blockIdx.y * BM;
    const int colBase = blockIdx.x * BN;

    uint32_t sA[NSTAGE], sB[NSTAGE];
#pragma unroll
    for (int s = 0; s < NSTAGE; s++) {
        sA[s] = smem_u32(smem + s * STAGE_HALVES);
        sB[s] = sA[s] + TILE_HALVES * 2;   // bytes
    }

    // Loader: 16B chunk = 8 halves. A tile: 128 rows x 8 chunks = 1024 chunks,
    // 4 per thread; B likewise. One commit_group per stage.
    auto load_stage = [&](int s, int k0) {
#pragma unroll
        for (int l = 0; l < 4; l++) {
            const int ch  = tid + 256 * l;
            const int row = ch >> 3;
            const int c16 = ch & 7;
            cp_async16(sA[s] + (uint32_t)(row * AST + c16 * 8) * 2,
                       &g_Wh[(size_t)(rowBase + row) * OUT_F + k0 + c16 * 8]);
        }
#pragma unroll
        for (int l = 0; l < 4; l++) {
            const int ch  = tid + 256 * l;
            const int row = ch >> 3;
            const int c16 = ch & 7;
            cp_async16(sB[s] + (uint32_t)(row * AST + c16 * 8) * 2,
                       &g_XTh[(size_t)(colBase + row) * OUT_F + k0 + c16 * 8]);
        }
        cp_commit();
    };

    float acc[4][4][4];
#pragma unroll
    for (int i = 0; i < 4; i++)
#pragma unroll
        for (int j = 0; j < 4; j++)
#pragma unroll
            for (int q = 0; q < 4; q++) acc[i][j][q] = 0.f;

    // Prologue: prefetch tile 0.
    load_stage(0, 0);

    for (int t = 0; t < NT; t++) {
        const int cur = t & 1;
        cp_wait<0>();                  // tile t resident (its load overlapped
                                       // the full compute phase of t-1)
        __syncthreads();               // all warps done with stage (t-1)&1

        if (t + 1 < NT) load_stage(cur ^ 1, (t + 1) * BK);

        const __half* Ab = reinterpret_cast<const __half*>(smem) + cur * STAGE_HALVES;
        const __half* Bb = Ab + TILE_HALVES;
#pragma unroll
        for (int ks = 0; ks < 4; ks++) {
            const int kh = ks * 16 + c * 4;
            unsigned afr[4][4], bfr[4][2];
#pragma unroll
            for (int i = 0; i < 4; i++) {
                const int m = wm * 64 + i * 16 + r;
                uint2 p0 = *reinterpret_cast<const uint2*>(&Ab[m * AST + kh]);
                uint2 p1 = *reinterpret_cast<const uint2*>(&Ab[(m + 8) * AST + kh]);
                afr[i][0] = p0.x;
                afr[i][1] = p1.x;
                afr[i][2] = p0.y;
                afr[i][3] = p1.y;
            }
#pragma unroll
            for (int j = 0; j < 4; j++) {
                const int n = wn * 32 + j * 8 + r;
                uint2 q = *reinterpret_cast<const uint2*>(&Bb[n * AST + kh]);
                bfr[j][0] = q.x;
                bfr[j][1] = q.y;
            }
#pragma unroll
            for (int i = 0; i < 4; i++)
#pragma unroll
                for (int j = 0; j < 4; j++)
                    mma_f16(acc[i][j], afr[i], bfr[j]);
        }
    }

    // Epilogue: bias add + float2 stores.
    float2 bv[4];
#pragma unroll
    for (int j = 0; j < 4; j++)
        bv[j] = *reinterpret_cast<const float2*>(&bias[colBase + wn * 32 + j * 8 + c2]);
#pragma unroll
    for (int i = 0; i < 4; i++) {
        const int row0 = rowBase + wm * 64 + i * 16 + r;
#pragma unroll
        for (int j = 0; j < 4; j++) {
            const int col = colBase + wn * 32 + j * 8 + c2;
            float2 o0 = make_float2(acc[i][j][0] + bv[j].x, acc[i][j][1] + bv[j].y);
            float2 o1 = make_float2(acc[i][j][2] + bv[j].x, acc[i][j][3] + bv[j].y);
            *reinterpret_cast<float2*>(&C[(size_t)row0 * NCOLS + col])       = o0;
            *reinterpret_cast<float2*>(&C[(size_t)(row0 + 8) * NCOLS + col]) = o1;
        }
    }
}

// ---------------------------------------------------------------------------
// Launch
// ---------------------------------------------------------------------------
extern "C" void kernel_launch(void* const* d_in, const int* in_sizes, int n_in,
                              void* d_out, int out_size) {
    const float* x    = (const float*)d_in[0];
    const int*   rows = (const int*)d_in[1];
    const int*   cols = (const int*)d_in[2];
    const float* vals = (const float*)d_in[3];
    const float* bias = (const float*)d_in[4];
    float*       y    = (float*)d_out;
    const int nnz = in_sizes[1];

    cudaFuncSetAttribute(gemm_f16_kernel,
                         cudaFuncAttributeMaxDynamicSharedMemorySize, SMEM_TOTAL);

    zero_Wh_kernel<<<1184, 256>>>();
    scatter_half_kernel<<<(nnz + 255) / 256, 256>>>(rows, cols, vals, nnz);
    transpose_convert_perm_kernel<<<dim3(NCOLS / 32, OUT_F / 32), dim3(32, 8)>>>(x);

    dim3 grid(NCOLS / BN, IN_F / BM);  // 32 x 32 = 1024 CTAs
    gemm_f16_kernel<<<grid, 256, SMEM_TOTAL>>>(bias, y);
}